// round 1
// baseline (speedup 1.0000x reference)
#include <cuda_runtime.h>

// Problem constants
#define SEQ   2048
#define BATCH 128
#define EDIM  128
#define LDIM  128
#define GDIM  512   // 4*L
#define NCLS  2

typedef unsigned long long ull;

// ---- packed fp32x2 helpers (Blackwell f32x2 datapath, PTX-only) ----
__device__ __forceinline__ ull ffma2(ull a, ull b, ull c) {
    ull d;
    asm("fma.rn.f32x2 %0, %1, %2, %3;" : "=l"(d) : "l"(a), "l"(b), "l"(c));
    return d;
}
__device__ __forceinline__ ull pack2(float lo, float hi) {
    ull r; asm("mov.b64 %0, {%1, %2};" : "=l"(r) : "f"(lo), "f"(hi)); return r;
}
__device__ __forceinline__ float2 unpack2(ull v) {
    float2 f; asm("mov.b64 {%0, %1}, %2;" : "=f"(f.x), "=f"(f.y) : "l"(v));
    return f;
}

// 536 MB scratch for precomputed input projections xg[t][b][g]
__device__ float g_xg[(size_t)SEQ * BATCH * GDIM];

// ============================================================
// Phase 1: xg = x @ Wi + bi    ([262144 x 128] * [128 x 512])
// Tile 64 rows x 128 cols per block, 256 threads, 4x8 outputs/thread,
// f32x2-paired over K (separate even/odd accumulators).
// ============================================================
#define TM 64
#define TN 128
#define BS_STRIDE 130   // padded to keep smem write conflicts low + 8B align

__global__ __launch_bounds__(256, 2)
void xproj_kernel(const float* __restrict__ x, const float* __restrict__ Wi,
                  const float* __restrict__ bi) {
    extern __shared__ float sm[];
    float* As = sm;                 // [64][128] row-major
    float* Bs = sm + TM * EDIM;     // [128 cols][130] = Wi transposed (K contiguous)

    const int tid = threadIdx.x;
    const size_t row0 = (size_t)blockIdx.x * TM;
    const int c0 = blockIdx.y * TN;

    // A tile: rows are contiguous in x -> one contiguous 32KB block
    {
        const float4* xa = (const float4*)(x + row0 * EDIM);
        float4* As4 = (float4*)As;
        #pragma unroll
        for (int i = 0; i < 8; i++) As4[tid + 256 * i] = xa[tid + 256 * i];
    }
    // B tile: Bs[c][k] = Wi[k][c0+c]  (transpose in smem so K is contiguous)
    {
        const int c  = tid & 127;
        const int kh = tid >> 7;    // 0 or 1
        for (int it = 0; it < 64; it++) {
            int k = it * 2 + kh;
            Bs[c * BS_STRIDE + k] = Wi[k * GDIM + c0 + c];
        }
    }
    __syncthreads();

    const int tx = tid & 15;    // 16 col-groups of 8
    const int ty = tid >> 4;    // 16 row-groups of 4
    const int rbase = ty * 4;
    const int cbase = tx * 8;

    ull acc[4][8];
    #pragma unroll
    for (int i = 0; i < 4; i++)
        #pragma unroll
        for (int j = 0; j < 8; j++) acc[i][j] = 0ULL;

    #pragma unroll 8
    for (int kk = 0; kk < 64; kk++) {       // k-pairs
        ull a2[4], b2[8];
        #pragma unroll
        for (int i = 0; i < 4; i++)
            a2[i] = *(const ull*)&As[(rbase + i) * EDIM + 2 * kk];
        #pragma unroll
        for (int j = 0; j < 8; j++)
            b2[j] = *(const ull*)&Bs[(cbase + j) * BS_STRIDE + 2 * kk];
        #pragma unroll
        for (int i = 0; i < 4; i++)
            #pragma unroll
            for (int j = 0; j < 8; j++)
                acc[i][j] = ffma2(a2[i], b2[j], acc[i][j]);
    }

    float bival[8];
    #pragma unroll
    for (int j = 0; j < 8; j++) bival[j] = bi[c0 + cbase + j];

    #pragma unroll
    for (int i = 0; i < 4; i++) {
        float outv[8];
        #pragma unroll
        for (int j = 0; j < 8; j++) {
            float2 p = unpack2(acc[i][j]);
            outv[j] = p.x + p.y + bival[j];
        }
        size_t base = (row0 + rbase + i) * (size_t)GDIM + (size_t)(c0 + cbase);
        *(float4*)&g_xg[base]     = make_float4(outv[0], outv[1], outv[2], outv[3]);
        *(float4*)&g_xg[base + 4] = make_float4(outv[4], outv[5], outv[6], outv[7]);
    }
}

// ============================================================
// Phase 2: persistent LSTM recurrence. One CTA per batch element,
// 512 threads = one thread per gate column. Wh column split:
//   k-pairs [0,44)  -> registers (88 regs/thread)
//   k-pairs [44,64) -> shared memory (80 KB)
// h broadcast from smem; f32x2-paired dot over K.
// ============================================================
#define WREG  44
#define WSMEM 20

__global__ __launch_bounds__(512, 1)
void lstm_kernel(const float* __restrict__ Wh, const float* __restrict__ bh,
                 const float* __restrict__ Wc, const float* __restrict__ bc,
                 float* __restrict__ out) {
    extern __shared__ char smraw[];
    float* hs   = (float*)smraw;                  // [128] hidden state (16B aligned)
    float* acts = (float*)(smraw + 512);          // [512] activated gates
    ull*   ws   = (ull*)(smraw + 512 + 2048);     // [WSMEM * 512] weight pairs

    const int g = threadIdx.x;     // gate column 0..511
    const int b = blockIdx.x;      // batch element

    // Load register-resident weight pairs: (Wh[2j][g], Wh[2j+1][g])
    ull wr[WREG];
    #pragma unroll
    for (int j = 0; j < WREG; j++)
        wr[j] = pack2(Wh[(2 * j) * GDIM + g], Wh[(2 * j + 1) * GDIM + g]);
    // Smem-resident weight pairs (k-pairs 44..63)
    #pragma unroll
    for (int j = 0; j < WSMEM; j++) {
        int kk = WREG + j;
        ws[j * GDIM + g] = pack2(Wh[(2 * kk) * GDIM + g],
                                 Wh[(2 * kk + 1) * GDIM + g]);
    }
    const float bhv = bh[g];
    if (g < LDIM) hs[g] = 0.0f;
    float c_state = 0.0f;
    __syncthreads();

    const float* xg_ptr = g_xg + (size_t)b * GDIM + g;

    for (int t = 0; t < SEQ; t++) {
        // prefetch this step's input projection (hidden under the dot)
        float xgv = __ldcs(xg_ptr + (size_t)t * (BATCH * GDIM));

        const ulonglong2* hq = (const ulonglong2*)hs;  // 2 h-pairs per load
        ull acc0 = 0ULL, acc1 = 0ULL;
        #pragma unroll
        for (int j = 0; j < WREG / 2; j++) {           // k-pairs 0..43
            ulonglong2 hh = hq[j];
            acc0 = ffma2(wr[2 * j],     hh.x, acc0);
            acc1 = ffma2(wr[2 * j + 1], hh.y, acc1);
        }
        #pragma unroll
        for (int j = 0; j < WSMEM / 2; j++) {          // k-pairs 44..63
            ulonglong2 hh = hq[WREG / 2 + j];
            acc0 = ffma2(ws[(2 * j) * GDIM + g],     hh.x, acc0);
            acc1 = ffma2(ws[(2 * j + 1) * GDIM + g], hh.y, acc1);
        }
        float2 p0 = unpack2(acc0), p1 = unpack2(acc1);
        float gate = p0.x + p0.y + p1.x + p1.y + xgv + bhv;

        // each thread activates its own gate (spreads MUFU work over 512 threads)
        float a;
        if (g >= 2 * LDIM && g < 3 * LDIM) a = tanhf(gate);           // g-gate
        else                               a = 1.0f / (1.0f + __expf(-gate));
        acts[g] = a;
        __syncthreads();

        if (g < LDIM) {   // thread l owns c[l]
            float f  = acts[g];
            float ii = acts[LDIM + g];
            float gg = acts[2 * LDIM + g];
            float o  = acts[3 * LDIM + g];
            c_state = f * c_state + ii * gg;
            hs[g]   = o * tanhf(c_state);
        }
        __syncthreads();
    }

    // Final classifier: out[b][c] = h . Wc[:,c] + bc[c]
    if (g < NCLS) {
        float sum = bc[g];
        #pragma unroll 8
        for (int l = 0; l < LDIM; l++) sum += hs[l] * Wc[l * NCLS + g];
        out[b * NCLS + g] = sum;
    }
}

// ============================================================
// Launch
// ============================================================
extern "C" void kernel_launch(void* const* d_in, const int* in_sizes, int n_in,
                              void* d_out, int out_size) {
    const float* x  = (const float*)d_in[0];
    const float* Wi = (const float*)d_in[1];
    const float* bi = (const float*)d_in[2];
    const float* Wh = (const float*)d_in[3];
    const float* bh = (const float*)d_in[4];
    const float* Wc = (const float*)d_in[5];
    const float* bc = (const float*)d_in[6];
    float* out = (float*)d_out;

    const int smem1 = (TM * EDIM + TN * BS_STRIDE) * 4;          // 99,328 B
    const int smem2 = 512 + 2048 + WSMEM * GDIM * 8;             // 84,480 B
    cudaFuncSetAttribute(xproj_kernel,
                         cudaFuncAttributeMaxDynamicSharedMemorySize, smem1);
    cudaFuncSetAttribute(lstm_kernel,
                         cudaFuncAttributeMaxDynamicSharedMemorySize, smem2);

    dim3 grid1((SEQ * BATCH) / TM, GDIM / TN);   // 4096 x 4
    xproj_kernel<<<grid1, 256, smem1>>>(x, Wi, bi);
    lstm_kernel<<<BATCH, 512, smem2>>>(Wh, bh, Wc, bc, out);
}

// round 2
// speedup vs baseline: 1.2259x; 1.2259x over previous
#include <cuda_runtime.h>

// Problem constants
#define SEQ   2048
#define BATCH 128
#define EDIM  128
#define LDIM  128
#define GDIM  512   // 4*L
#define NCLS  2

typedef unsigned long long ull;

// ---- packed fp32x2 helpers (Blackwell f32x2 datapath, PTX-only) ----
__device__ __forceinline__ ull ffma2(ull a, ull b, ull c) {
    ull d;
    asm("fma.rn.f32x2 %0, %1, %2, %3;" : "=l"(d) : "l"(a), "l"(b), "l"(c));
    return d;
}
__device__ __forceinline__ ull pack2(float lo, float hi) {
    ull r; asm("mov.b64 %0, {%1, %2};" : "=l"(r) : "f"(lo), "f"(hi)); return r;
}
__device__ __forceinline__ float2 unpack2(ull v) {
    float2 f; asm("mov.b64 {%0, %1}, %2;" : "=f"(f.x), "=f"(f.y) : "l"(v));
    return f;
}

// 512 MB scratch for precomputed input projections xg[t][b][g]
__device__ float g_xg[(size_t)SEQ * BATCH * GDIM];

// ============================================================
// Phase 1: xg = x @ Wi + bi    ([262144 x 128] * [128 x 512])
// Tile 64 rows x 128 cols per block, 256 threads, 4x8 outputs/thread.
// Columns STRIDED per thread (col = tx + 16j) so the b2 smem loads are
// bank-conflict-free: lane stride = 65 ull == 1 (mod 16 superbanks).
// ============================================================
#define TM 64
#define TN 128
#define BS_STRIDE 130   // floats; 65 ull (odd -> conflict-free across cols)

__global__ __launch_bounds__(256, 2)
void xproj_kernel(const float* __restrict__ x, const float* __restrict__ Wi,
                  const float* __restrict__ bi) {
    extern __shared__ float sm[];
    float* As = sm;                 // [64][128] row-major
    float* Bs = sm + TM * EDIM;     // [128 cols][130] = Wi transposed (K contiguous)

    const int tid = threadIdx.x;
    const size_t row0 = (size_t)blockIdx.x * TM;
    const int c0 = blockIdx.y * TN;

    // A tile: 64 contiguous rows of x -> one contiguous 32KB block
    {
        const float4* xa = (const float4*)(x + row0 * EDIM);
        float4* As4 = (float4*)As;
        #pragma unroll
        for (int i = 0; i < 8; i++) As4[tid + 256 * i] = xa[tid + 256 * i];
    }
    // B tile: Bs[c][k] = Wi[k][c0+c]  (transpose so K is contiguous)
    {
        const int c  = tid & 127;
        const int kh = tid >> 7;    // 0 or 1
        #pragma unroll 8
        for (int it = 0; it < 64; it++) {
            int k = it * 2 + kh;
            Bs[c * BS_STRIDE + k] = Wi[k * GDIM + c0 + c];
        }
    }
    __syncthreads();

    const int tx = tid & 15;    // columns: tx + 16j, j in [0,8)
    const int ty = tid >> 4;    // row group
    const int rbase = ty * 4;

    ull acc[4][8];
    #pragma unroll
    for (int i = 0; i < 4; i++)
        #pragma unroll
        for (int j = 0; j < 8; j++) acc[i][j] = 0ULL;

    const ull* ap = (const ull*)&As[rbase * EDIM];          // a pairs
    const ull* bp = (const ull*)&Bs[tx * BS_STRIDE];        // b pairs (col tx)
    const int BSU = BS_STRIDE / 2;                          // 65 ull per col

    #pragma unroll 8
    for (int kk = 0; kk < 64; kk++) {       // k-pairs
        ull a2[4], b2[8];
        #pragma unroll
        for (int i = 0; i < 4; i++) a2[i] = ap[i * (EDIM / 2) + kk];
        #pragma unroll
        for (int j = 0; j < 8; j++) b2[j] = bp[j * 16 * BSU + kk];
        #pragma unroll
        for (int i = 0; i < 4; i++)
            #pragma unroll
            for (int j = 0; j < 8; j++)
                acc[i][j] = ffma2(a2[i], b2[j], acc[i][j]);
    }

    float bival[8];
    #pragma unroll
    for (int j = 0; j < 8; j++) bival[j] = bi[c0 + tx + 16 * j];

    #pragma unroll
    for (int i = 0; i < 4; i++) {
        size_t base = (row0 + rbase + i) * (size_t)GDIM + (size_t)(c0 + tx);
        #pragma unroll
        for (int j = 0; j < 8; j++) {
            float2 p = unpack2(acc[i][j]);
            g_xg[base + 16 * j] = p.x + p.y + bival[j];
        }
    }
}

// ============================================================
// Phase 2: persistent LSTM recurrence. One CTA per batch element,
// 512 threads. Gate remap: thread tid -> gate column (tid&3)*128 + tid/4,
// so f,i,g,o of hidden unit u live in 4 ADJACENT lanes -> combined with
// 3 shfl.xor (no acts smem round, no second barrier).
// Double-buffered h -> exactly ONE __syncthreads per step.
// Wh k-pairs: [0,42) in registers (84 regs), [42,64) in smem (indexed by tid).
// ============================================================
#define WREG  42
#define WSMEM 22

__global__ __launch_bounds__(512, 1)
void lstm_kernel(const float* __restrict__ Wh, const float* __restrict__ bh,
                 const float* __restrict__ Wc, const float* __restrict__ bc,
                 float* __restrict__ out) {
    extern __shared__ char smraw[];
    float* hbuf = (float*)smraw;                  // [2][128] double-buffered h
    ull*   ws   = (ull*)(smraw + 1024);           // [WSMEM][512] weight pairs

    const int tid = threadIdx.x;
    const int b   = blockIdx.x;
    const int q   = tid & 3;        // gate type: 0=f 1=i 2=g 3=o
    const int u   = tid >> 2;       // hidden unit
    const int g   = q * LDIM + u;   // gate column in Wh/bh/xg order

    // Register-resident weight pairs: (Wh[2j][g], Wh[2j+1][g])
    ull wr[WREG];
    #pragma unroll
    for (int j = 0; j < WREG; j++)
        wr[j] = pack2(Wh[(2 * j) * GDIM + g], Wh[(2 * j + 1) * GDIM + g]);
    // Smem-resident weight pairs, slot indexed by tid (conflict-free reads)
    #pragma unroll
    for (int j = 0; j < WSMEM; j++) {
        int kk = WREG + j;
        ws[j * 512 + tid] = pack2(Wh[(2 * kk) * GDIM + g],
                                  Wh[(2 * kk + 1) * GDIM + g]);
    }
    const float bhv = bh[g];
    if (tid < LDIM) hbuf[tid] = 0.0f;             // buffer 0 = h_0 = 0
    float c_state = 0.0f;
    __syncthreads();

    const float* xg_ptr = g_xg + (size_t)b * GDIM + g;
    const unsigned FULL = 0xFFFFFFFFu;
    const float gmul = (q == 2) ? 2.0f : 1.0f;    // tanh = 2*sig(2x)-1

    const float* hr = hbuf;           // read buffer
    float*       hw = hbuf + LDIM;    // write buffer

    float xgv = __ldcs(xg_ptr);       // t = 0 projection

    for (int t = 0; t < SEQ; t++) {
        // prefetch next step's input projection (hidden under the dot)
        int tn = (t + 1) & (SEQ - 1);
        float xg_next = __ldcs(xg_ptr + (size_t)tn * (BATCH * GDIM));

        const ulonglong2* hq = (const ulonglong2*)hr;  // 4 h values per load
        ull acc0 = 0ULL, acc1 = 0ULL, acc2 = 0ULL, acc3 = 0ULL;
        #pragma unroll
        for (int j = 0; j < WREG / 2; j++) {           // k-pairs 0..41
            ulonglong2 hh = hq[j];
            if (j & 1) {
                acc2 = ffma2(wr[2 * j],     hh.x, acc2);
                acc3 = ffma2(wr[2 * j + 1], hh.y, acc3);
            } else {
                acc0 = ffma2(wr[2 * j],     hh.x, acc0);
                acc1 = ffma2(wr[2 * j + 1], hh.y, acc1);
            }
        }
        #pragma unroll
        for (int j = 0; j < WSMEM / 2; j++) {          // k-pairs 42..63
            ulonglong2 hh = hq[WREG / 2 + j];
            if (j & 1) {
                acc2 = ffma2(ws[(2 * j) * 512 + tid],     hh.x, acc2);
                acc3 = ffma2(ws[(2 * j + 1) * 512 + tid], hh.y, acc3);
            } else {
                acc0 = ffma2(ws[(2 * j) * 512 + tid],     hh.x, acc0);
                acc1 = ffma2(ws[(2 * j + 1) * 512 + tid], hh.y, acc1);
            }
        }
        float2 p0 = unpack2(acc0), p1 = unpack2(acc1);
        float2 p2 = unpack2(acc2), p3 = unpack2(acc3);
        float gate = ((p0.x + p0.y) + (p1.x + p1.y))
                   + ((p2.x + p2.y) + (p3.x + p3.y)) + xgv + bhv;

        // unified activation: sig for f,i,o; tanh (=2*sig(2x)-1) for g-gate
        float e = __expf(-gmul * gate);
        float s = __fdividef(1.0f, 1.0f + e);
        float a = (q == 2) ? (2.0f * s - 1.0f) : s;

        // allgather the 4 gate acts within each 4-lane nibble (3 shuffles)
        float a1 = __shfl_xor_sync(FULL, a, 1);
        float lo = (q & 1) ? a1 : a;    // act of even member of pair
        float hi = (q & 1) ? a  : a1;   // act of odd member
        float lo2 = __shfl_xor_sync(FULL, lo, 2);
        float hi2 = __shfl_xor_sync(FULL, hi, 2);
        float f_ = (q & 2) ? lo2 : lo;
        float i_ = (q & 2) ? hi2 : hi;
        float g_ = (q & 2) ? lo  : lo2;
        float o_ = (q & 2) ? hi  : hi2;

        c_state = f_ * c_state + i_ * g_;           // replicated in all 4 lanes
        float e2 = __expf(-2.0f * c_state);
        float th = __fdividef(1.0f - e2, 1.0f + e2);
        float h  = o_ * th;
        if (q == 0) hw[u] = h;

        xgv = xg_next;
        __syncthreads();
        // swap buffers
        const float* tmp = hr; hr = hw; hw = (float*)tmp;
    }

    // Final classifier: out[b][c] = h . Wc[:,c] + bc[c]
    if (tid < NCLS) {
        float sum = bc[tid];
        #pragma unroll 8
        for (int l = 0; l < LDIM; l++) sum += hr[l] * Wc[l * NCLS + tid];
        out[b * NCLS + tid] = sum;
    }
}

// ============================================================
// Launch
// ============================================================
extern "C" void kernel_launch(void* const* d_in, const int* in_sizes, int n_in,
                              void* d_out, int out_size) {
    const float* x  = (const float*)d_in[0];
    const float* Wi = (const float*)d_in[1];
    const float* bi = (const float*)d_in[2];
    const float* Wh = (const float*)d_in[3];
    const float* bh = (const float*)d_in[4];
    const float* Wc = (const float*)d_in[5];
    const float* bc = (const float*)d_in[6];
    float* out = (float*)d_out;

    const int smem1 = (TM * EDIM + TN * BS_STRIDE) * 4;          // 99,328 B
    const int smem2 = 1024 + WSMEM * 512 * 8;                    // 91,136 B
    cudaFuncSetAttribute(xproj_kernel,
                         cudaFuncAttributeMaxDynamicSharedMemorySize, smem1);
    cudaFuncSetAttribute(lstm_kernel,
                         cudaFuncAttributeMaxDynamicSharedMemorySize, smem2);

    dim3 grid1((SEQ * BATCH) / TM, GDIM / TN);   // 4096 x 4
    xproj_kernel<<<grid1, 256, smem1>>>(x, Wi, bi);
    lstm_kernel<<<BATCH, 512, smem2>>>(Wh, bh, Wc, bc, out);
}

// round 12
// speedup vs baseline: 1.6969x; 1.3842x over previous
#include <cuda_runtime.h>

// Problem constants
#define SEQ   2048
#define BATCH 128
#define EDIM  128
#define LDIM  128
#define GDIM  512   // 4*L
#define NCLS  2

typedef unsigned long long ull;

// ---- packed fp32x2 helpers (Blackwell f32x2 datapath, PTX-only) ----
__device__ __forceinline__ ull ffma2(ull a, ull b, ull c) {
    ull d;
    asm("fma.rn.f32x2 %0, %1, %2, %3;" : "=l"(d) : "l"(a), "l"(b), "l"(c));
    return d;
}
__device__ __forceinline__ ull pack2(float lo, float hi) {
    ull r; asm("mov.b64 %0, {%1, %2};" : "=l"(r) : "f"(lo), "f"(hi)); return r;
}
__device__ __forceinline__ float2 unpack2(ull v) {
    float2 f; asm("mov.b64 {%0, %1}, %2;" : "=f"(f.x), "=f"(f.y) : "l"(v));
    return f;
}
__device__ __forceinline__ float hsum2(ull v) {
    float2 p = unpack2(v); return p.x + p.y;
}

// 512 MB scratch for precomputed input projections xg[t][b][g]
__device__ float g_xg[(size_t)SEQ * BATCH * GDIM];

// ============================================================
// Phase 1: xg = x @ Wi + bi    ([262144 x 128] * [128 x 512])
// Tile 64 rows x 128 cols, 128 threads, 8x8 outputs/thread.
// Per warp per k-pair: 16 a-wavefronts + 16 b-wavefronts = 32 LDS wf
// vs 64 FFMA2 = 32 issue cyc -> LDS/FMA balanced.
// Columns strided (col = tx + 16j): stride 130 floats -> conflict-free.
// ============================================================
#define TM 64
#define TN 128
#define BS_STRIDE 130

__global__ __launch_bounds__(128, 2)
void xproj_kernel(const float* __restrict__ x, const float* __restrict__ Wi,
                  const float* __restrict__ bi) {
    extern __shared__ float sm[];
    float* As = sm;                 // [64][128]
    float* Bs = sm + TM * EDIM;     // [128 cols][130] transposed Wi slice

    const int tid = threadIdx.x;
    const size_t row0 = (size_t)blockIdx.x * TM;
    const int c0 = blockIdx.y * TN;

    // A tile: 64 contiguous rows of x (32KB)
    {
        const float4* xa = (const float4*)(x + row0 * EDIM);
        float4* As4 = (float4*)As;
        #pragma unroll
        for (int i = 0; i < 16; i++) As4[tid + 128 * i] = xa[tid + 128 * i];
    }
    // B tile: Bs[c][k] = Wi[k][c0+c]; thread = column c (coalesced across c)
    {
        const int c = tid;
        #pragma unroll 8
        for (int k = 0; k < EDIM; k++)
            Bs[c * BS_STRIDE + k] = Wi[k * GDIM + c0 + c];
    }
    __syncthreads();

    const int tx = tid & 15;    // columns tx + 16j, j<8
    const int ty = tid >> 4;    // row group, rows ty*8 + i, i<8
    const int rbase = ty * 8;

    ull acc[8][8];
    #pragma unroll
    for (int i = 0; i < 8; i++)
        #pragma unroll
        for (int j = 0; j < 8; j++) acc[i][j] = 0ULL;

    const ull* ap = (const ull*)&As[rbase * EDIM];
    const ull* bp = (const ull*)&Bs[tx * BS_STRIDE];
    const int BSU = BS_STRIDE / 2;   // 65 ull per column

    #pragma unroll 2
    for (int kk = 0; kk < 64; kk++) {
        ull a2[8], b2[8];
        #pragma unroll
        for (int i = 0; i < 8; i++) a2[i] = ap[i * (EDIM / 2) + kk];
        #pragma unroll
        for (int j = 0; j < 8; j++) b2[j] = bp[j * 16 * BSU + kk];
        #pragma unroll
        for (int i = 0; i < 8; i++)
            #pragma unroll
            for (int j = 0; j < 8; j++)
                acc[i][j] = ffma2(a2[i], b2[j], acc[i][j]);
    }

    float bival[8];
    #pragma unroll
    for (int j = 0; j < 8; j++) bival[j] = bi[c0 + tx + 16 * j];

    #pragma unroll
    for (int i = 0; i < 8; i++) {
        size_t base = (row0 + rbase + i) * (size_t)GDIM + (size_t)(c0 + tx);
        #pragma unroll
        for (int j = 0; j < 8; j++)
            g_xg[base + 16 * j] = hsum2(acc[i][j]) + bival[j];
    }
}

// ============================================================
// Phase 2: persistent LSTM. One CTA per batch, 256 threads,
// 2 gate columns per thread:
//   half = tid>>7, u = tid&127
//   col A = half*128 + u   (f for half0, i for half1)
//   col B = 256 + col A    (g~ for half0, o for half1)
// Weights per column: 46 k-pairs in registers (184 regs),
// 18 k-pairs in smem (72KB -> 576 LDS cyc/step).
// h broadcast: 32 LDS.128 x 8 warps = 256 cyc/step.
// Tail: act exchange via smem float2, c-update on half0 threads.
// ============================================================
#define WREG  46                    // reg k-pairs per column (even)
#define WSM   (64 - WREG)           // 18 smem k-pairs per column
#define NJJ   (WREG / 2)            // 23 reg jj iterations
#define SJJ   (WSM / 2)             // 9 smem jj iterations

__global__ __launch_bounds__(256, 1)
void lstm_kernel(const float* __restrict__ Wh, const float* __restrict__ bh,
                 const float* __restrict__ Wc, const float* __restrict__ bc,
                 float* __restrict__ out) {
    extern __shared__ char smraw[];
    float*      hs   = (float*)smraw;                   // [128] hidden state
    float2*     xch  = (float2*)(smraw + 512);          // [128] (i,o) exchange
    ulonglong2* wsA  = (ulonglong2*)(smraw + 512 + 1024);            // [SJJ][256]
    ulonglong2* wsB  = wsA + SJJ * 256;                               // [SJJ][256]

    const int tid  = threadIdx.x;
    const int b    = blockIdx.x;
    const int half = tid >> 7;       // 0: f,g~   1: i,o
    const int u    = tid & 127;      // hidden unit
    const int gA   = half * LDIM + u;
    const int gB   = 2 * LDIM + gA;

    // Register weights: pair p of col = (Wh[2p][g], Wh[2p+1][g])
    ull wrA[WREG], wrB[WREG];
    #pragma unroll
    for (int p = 0; p < WREG; p++) {
        wrA[p] = pack2(Wh[(2 * p) * GDIM + gA], Wh[(2 * p + 1) * GDIM + gA]);
        wrB[p] = pack2(Wh[(2 * p) * GDIM + gB], Wh[(2 * p + 1) * GDIM + gB]);
    }
    // Smem weights: jj covers k-pairs (2jj, 2jj+1), jj in [NJJ, 32)
    #pragma unroll
    for (int s = 0; s < SJJ; s++) {
        int p0 = WREG + 2 * s, p1 = p0 + 1;
        ulonglong2 va, vb;
        va.x = pack2(Wh[(2 * p0) * GDIM + gA], Wh[(2 * p0 + 1) * GDIM + gA]);
        va.y = pack2(Wh[(2 * p1) * GDIM + gA], Wh[(2 * p1 + 1) * GDIM + gA]);
        vb.x = pack2(Wh[(2 * p0) * GDIM + gB], Wh[(2 * p0 + 1) * GDIM + gB]);
        vb.y = pack2(Wh[(2 * p1) * GDIM + gB], Wh[(2 * p1 + 1) * GDIM + gB]);
        wsA[s * 256 + tid] = va;
        wsB[s * 256 + tid] = vb;
    }
    const float bhA = bh[gA];
    const float bhB = bh[gB];
    if (tid < LDIM) hs[tid] = 0.0f;
    float c_state = 0.0f;
    __syncthreads();

    const float* xgA_ptr = g_xg + (size_t)b * GDIM + gA;
    const float* xgB_ptr = g_xg + (size_t)b * GDIM + gB;
    float xgA = __ldcs(xgA_ptr);
    float xgB = __ldcs(xgB_ptr);

    for (int t = 0; t < SEQ; t++) {
        // prefetch next step's projections (hide under the dot)
        size_t noff = (size_t)((t + 1) & (SEQ - 1)) * (BATCH * GDIM);
        float xgA_n = __ldcs(xgA_ptr + noff);
        float xgB_n = __ldcs(xgB_ptr + noff);

        const ulonglong2* hq = (const ulonglong2*)hs;   // broadcast .128
        ull a0 = 0ULL, a1 = 0ULL, b0 = 0ULL, b1 = 0ULL;
        #pragma unroll
        for (int jj = 0; jj < NJJ; jj++) {              // k-pairs 0..2*NJJ-1
            ulonglong2 hh = hq[jj];
            a0 = ffma2(wrA[2 * jj],     hh.x, a0);
            a1 = ffma2(wrA[2 * jj + 1], hh.y, a1);
            b0 = ffma2(wrB[2 * jj],     hh.x, b0);
            b1 = ffma2(wrB[2 * jj + 1], hh.y, b1);
        }
        #pragma unroll
        for (int s = 0; s < SJJ; s++) {                 // k-pairs WREG..63
            ulonglong2 hh = hq[NJJ + s];
            ulonglong2 wa = wsA[s * 256 + tid];
            ulonglong2 wb = wsB[s * 256 + tid];
            a0 = ffma2(wa.x, hh.x, a0);
            a1 = ffma2(wa.y, hh.y, a1);
            b0 = ffma2(wb.x, hh.x, b0);
            b1 = ffma2(wb.y, hh.y, b1);
        }
        float gateA = hsum2(a0) + hsum2(a1) + xgA + bhA;
        float gateB = hsum2(b0) + hsum2(b1) + xgB + bhB;

        // activations: half0 -> sig(f), tanh(g~); half1 -> sig(i), sig(o)
        float actA = __fdividef(1.0f, 1.0f + __expf(-gateA));
        float actB;
        if (half == 0) {
            float sg = __fdividef(1.0f, 1.0f + __expf(-2.0f * gateB));
            actB = 2.0f * sg - 1.0f;                    // tanh(g~)
        } else {
            actB = __fdividef(1.0f, 1.0f + __expf(-gateB));
        }

        if (half == 1) xch[u] = make_float2(actA, actB);   // (i, o)
        __syncthreads();

        if (half == 0) {                                // owns c[u], h[u]
            float2 io = xch[u];
            c_state = actA * c_state + io.x * actB;     // f*c + i*g~
            float sg = __fdividef(1.0f, 1.0f + __expf(-2.0f * c_state));
            hs[u] = io.y * (2.0f * sg - 1.0f);          // o * tanh(c)
        }
        xgA = xgA_n; xgB = xgB_n;
        __syncthreads();
    }

    // Final classifier
    if (tid < NCLS) {
        float sum = bc[tid];
        #pragma unroll 8
        for (int l = 0; l < LDIM; l++) sum += hs[l] * Wc[l * NCLS + tid];
        out[b * NCLS + tid] = sum;
    }
}

// ============================================================
// Launch
// ============================================================
extern "C" void kernel_launch(void* const* d_in, const int* in_sizes, int n_in,
                              void* d_out, int out_size) {
    const float* x  = (const float*)d_in[0];
    const float* Wi = (const float*)d_in[1];
    const float* bi = (const float*)d_in[2];
    const float* Wh = (const float*)d_in[3];
    const float* bh = (const float*)d_in[4];
    const float* Wc = (const float*)d_in[5];
    const float* bc = (const float*)d_in[6];
    float* out = (float*)d_out;

    const int smem1 = (TM * EDIM + TN * BS_STRIDE) * 4;      // 99,328 B
    const int smem2 = 512 + 1024 + 2 * SJJ * 256 * 16;       // 75,264 B
    cudaFuncSetAttribute(xproj_kernel,
                         cudaFuncAttributeMaxDynamicSharedMemorySize, smem1);
    cudaFuncSetAttribute(lstm_kernel,
                         cudaFuncAttributeMaxDynamicSharedMemorySize, smem2);

    dim3 grid1((SEQ * BATCH) / TM, GDIM / TN);   // 4096 x 4
    xproj_kernel<<<grid1, 128, smem1>>>(x, Wi, bi);
    lstm_kernel<<<BATCH, 256, smem2>>>(Wh, bh, Wc, bc, out);
}